// round 17
// baseline (speedup 1.0000x reference)
#include <cuda_runtime.h>
#include <cuda_bf16.h>
#include <cstdint>
#include <stdint.h>
#include <math.h>

// Problem constants
#define Dd 1024   // feature dim
#define Cc 1000   // prototypes
#define Bb 128    // batch
#define RT 1128   // Cc + Bb stacked rows
#define MP 1152   // RT padded to multiple of 64
#define KS 4      // split-K for cross-dot gemm
#define KC (Dd / KS)

// Scratch (device globals — no allocation allowed)
__device__ __nv_bfloat16 g_Abf[MP * Dd];   // [mu; x; 0] bf16
__device__ __nv_bfloat16 g_Bbf[Dd * Dd];   // tril(L) bf16, NATURAL [k][n] layout
__device__ __nv_bfloat16 g_MAbf[MP * Dd];  // MA = [mu;x] @ tril(L)
__device__ float g_q[MP];                  // ||MA_r||^2 + 1e-6||in_r||^2
__device__ float g_bd[RT];                 // beta . in_r
__device__ float g_part[KS * Bb * Dd];     // per-z cross-dot slices (no atomics)

// ---------------------------------------------------------------------------
// helpers
// ---------------------------------------------------------------------------
__device__ __forceinline__ void ldsm_x4(uint32_t* r, uint32_t addr) {
    asm volatile("ldmatrix.sync.aligned.m8n8.x4.shared.b16 {%0,%1,%2,%3}, [%4];\n"
                 : "=r"(r[0]), "=r"(r[1]), "=r"(r[2]), "=r"(r[3]) : "r"(addr));
}

__device__ __forceinline__ void ldsm_x4_trans(uint32_t* r, uint32_t addr) {
    asm volatile("ldmatrix.sync.aligned.m8n8.x4.trans.shared.b16 {%0,%1,%2,%3}, [%4];\n"
                 : "=r"(r[0]), "=r"(r[1]), "=r"(r[2]), "=r"(r[3]) : "r"(addr));
}

__device__ __forceinline__ void mma_bf16(float* d, const uint32_t* a,
                                         uint32_t b0, uint32_t b1) {
    asm volatile(
        "mma.sync.aligned.m16n8k16.row.col.f32.bf16.bf16.f32 "
        "{%0,%1,%2,%3}, {%4,%5,%6,%7}, {%8,%9}, {%0,%1,%2,%3};\n"
        : "+f"(d[0]), "+f"(d[1]), "+f"(d[2]), "+f"(d[3])
        : "r"(a[0]), "r"(a[1]), "r"(a[2]), "r"(a[3]), "r"(b0), "r"(b1));
}

// ---------------------------------------------------------------------------
// 0) prep (block-range dispatch):
//    [0, MP):        bf16 convert row of [mu;x;0] + input stats (seed g_q, g_bd)
//    [MP, MP+Dd):    row k of tril(L): pure elementwise convert, NO transpose.
//                    Only the live span n < 64*(k/64+1) is read/written.
// ---------------------------------------------------------------------------
__global__ __launch_bounds__(256) void prep(const float* __restrict__ x,
                                            const float* __restrict__ mu,
                                            const float* __restrict__ beta,
                                            const float* __restrict__ L) {
    int bid = blockIdx.x;
    int tid = threadIdx.x;

    if (bid < MP) {
        int r = bid;
        int k = tid * 4;
        float4 v = make_float4(0.f, 0.f, 0.f, 0.f);
        if (r < Cc)      v = *reinterpret_cast<const float4*>(mu + (size_t)r * Dd + k);
        else if (r < RT) v = *reinterpret_cast<const float4*>(x + (size_t)(r - Cc) * Dd + k);
        __nv_bfloat162 p0 = __floats2bfloat162_rn(v.x, v.y);
        __nv_bfloat162 p1 = __floats2bfloat162_rn(v.z, v.w);
        uint2 o;
        o.x = *reinterpret_cast<uint32_t*>(&p0);
        o.y = *reinterpret_cast<uint32_t*>(&p1);
        *reinterpret_cast<uint2*>(g_Abf + (size_t)r * Dd + k) = o;

        if (r >= RT) {
            if (tid == 0) g_q[r] = 0.f;
            return;
        }

        float4 b4 = *reinterpret_cast<const float4*>(beta + k);
        float sin_ = v.x * v.x + v.y * v.y + v.z * v.z + v.w * v.w;
        float sb = b4.x * v.x + b4.y * v.y + b4.z * v.z + b4.w * v.w;
#pragma unroll
        for (int off = 16; off > 0; off >>= 1) {
            sin_ += __shfl_xor_sync(0xFFFFFFFFu, sin_, off);
            sb += __shfl_xor_sync(0xFFFFFFFFu, sb, off);
        }
        __shared__ float red[2][8];
        int wid = tid >> 5, lane = tid & 31;
        if (lane == 0) { red[0][wid] = sin_; red[1][wid] = sb; }
        __syncthreads();
        if (tid == 0) {
            float t0 = 0.f, t1 = 0.f;
#pragma unroll
            for (int wq = 0; wq < 8; wq++) { t0 += red[0][wq]; t1 += red[1][wq]; }
            g_q[r] = 1e-6f * t0;   // seed; gemm epilogue atomically adds ||MA||^2
            g_bd[r] = t1;
        }
    } else {
        // ---- row k of tril(L): elementwise convert, natural [k][n] layout ----
        int k = bid - MP;                       // 0..1023
        int nlive = ((k >> 6) + 1) << 6;        // live span: n < nlive
        int n = tid * 4;
        if (n >= nlive) return;                 // dead 64-col chunks never read
        float4 v = *reinterpret_cast<const float4*>(L + (size_t)k * Dd + n);
        // tril mask: keep L[k][n] iff k >= n
        v.x = (n + 0 <= k) ? v.x : 0.f;
        v.y = (n + 1 <= k) ? v.y : 0.f;
        v.z = (n + 2 <= k) ? v.z : 0.f;
        v.w = (n + 3 <= k) ? v.w : 0.f;
        __nv_bfloat162 p0 = __floats2bfloat162_rn(v.x, v.y);
        __nv_bfloat162 p1 = __floats2bfloat162_rn(v.z, v.w);
        uint2 o;
        o.x = *reinterpret_cast<uint32_t*>(&p0);
        o.y = *reinterpret_cast<uint32_t*>(&p1);
        *reinterpret_cast<uint2*>(g_Bbf + (size_t)k * Dd + n) = o;
    }
}

// ---------------------------------------------------------------------------
// 1) gemm_ma_mma: g_MAbf[m][n] = sum_k g_Abf[m][k] * tril(L)[k][n]
//    A: [m][k] rows, non-trans ldsm (unchanged). B: natural [k][n] rows,
//    ldmatrix.trans fragments. BM=BN=64, BK=32, 128 thr, 2x2 warps,
//    warp tile 32x32, triangular K-skip. PDL.
// ---------------------------------------------------------------------------
__global__ __launch_bounds__(128) void gemm_ma_mma() {
    __shared__ __align__(16) __nv_bfloat16 As[64][40];
    __shared__ __align__(16) __nv_bfloat16 Bs[32][72];   // [k][n], pad 8
    int bm = blockIdx.x * 64;
    int bn = blockIdx.y * 64;
    int tid = threadIdx.x;
    int lane = tid & 31, w = tid >> 5;
    int wm = (w & 1) * 32, wn = (w >> 1) * 32;

    // A loads: 64 rows x 32 k, 2 threads/row
    int lr = tid >> 1;
    int lk = (tid & 1) * 16;
    const __nv_bfloat16* aptr = g_Abf + (size_t)(bm + lr) * Dd + lk;
    // B loads: 32 k-rows x 64 n, 4 threads/row (16-elem chunk each)
    int brow = tid >> 2;
    int bcol = (tid & 3) * 16;
    const __nv_bfloat16* bptr = g_Bbf + (size_t)brow * Dd + bn + bcol;

    float acc[2][4][4];
#pragma unroll
    for (int mt = 0; mt < 2; mt++)
#pragma unroll
        for (int nt = 0; nt < 4; nt++)
#pragma unroll
            for (int e = 0; e < 4; e++) acc[mt][nt][e] = 0.f;

    uint32_t aA[2], bA[2];
#pragma unroll
    for (int t2 = 0; t2 < 2; t2++) {
        aA[t2] = (uint32_t)__cvta_generic_to_shared(
            &As[wm + t2 * 16 + (lane & 15)][(lane >> 4) * 8]);
        // trans: lane&15 -> k row, (lane>>4)*8 -> n offset within 16-wide group
        bA[t2] = (uint32_t)__cvta_generic_to_shared(
            &Bs[lane & 15][wn + t2 * 16 + (lane >> 4) * 8]);
    }
    int kstart = bn;  // tril skip: B[k][n] = 0 for k < n

    cudaGridDependencySynchronize();   // wait for prep outputs

    uint4 pa0 = *reinterpret_cast<const uint4*>(aptr + kstart);
    uint4 pa1 = *reinterpret_cast<const uint4*>(aptr + kstart + 8);
    uint4 pb0 = *reinterpret_cast<const uint4*>(bptr + (size_t)kstart * Dd);
    uint4 pb1 = *reinterpret_cast<const uint4*>(bptr + (size_t)kstart * Dd + 8);

    for (int k0 = kstart; k0 < Dd; k0 += 32) {
        *reinterpret_cast<uint4*>(&As[lr][lk]) = pa0;
        *reinterpret_cast<uint4*>(&As[lr][lk + 8]) = pa1;
        *reinterpret_cast<uint4*>(&Bs[brow][bcol]) = pb0;
        *reinterpret_cast<uint4*>(&Bs[brow][bcol + 8]) = pb1;
        __syncthreads();
        if (k0 + 32 < Dd) {
            pa0 = *reinterpret_cast<const uint4*>(aptr + k0 + 32);
            pa1 = *reinterpret_cast<const uint4*>(aptr + k0 + 40);
            pb0 = *reinterpret_cast<const uint4*>(bptr + (size_t)(k0 + 32) * Dd);
            pb1 = *reinterpret_cast<const uint4*>(bptr + (size_t)(k0 + 32) * Dd + 8);
        }
#pragma unroll
        for (int ks = 0; ks < 2; ks++) {
            uint32_t aoff = (uint32_t)(ks * 32);          // 16 bf16 along k
            uint32_t boff = (uint32_t)(ks * 16 * 144);    // 16 k-rows * 144B
            uint32_t a0[4], a1[4], br0[4], br1[4];
            ldsm_x4(a0, aA[0] + aoff);
            ldsm_x4(a1, aA[1] + aoff);
            ldsm_x4_trans(br0, bA[0] + boff);
            ldsm_x4_trans(br1, bA[1] + boff);
#pragma unroll
            for (int mt = 0; mt < 2; mt++) {
                uint32_t* a = mt ? a1 : a0;
                // trans pairing: (r0,r1) = n-group0 k-low/high; (r2,r3) = n-group1
                mma_bf16(acc[mt][0], a, br0[0], br0[1]);
                mma_bf16(acc[mt][1], a, br0[2], br0[3]);
                mma_bf16(acc[mt][2], a, br1[0], br1[1]);
                mma_bf16(acc[mt][3], a, br1[2], br1[3]);
            }
        }
        __syncthreads();
    }

    int mrow = lane >> 2;
    int ncol = (lane & 3) * 2;
#pragma unroll
    for (int mt = 0; mt < 2; mt++) {
        float s0 = 0.f, s1 = 0.f;
        int row = bm + wm + mt * 16 + mrow;
#pragma unroll
        for (int nt = 0; nt < 4; nt++) {
            int col = bn + wn + nt * 8 + ncol;
            __nv_bfloat162 lo = __floats2bfloat162_rn(acc[mt][nt][0], acc[mt][nt][1]);
            __nv_bfloat162 hi = __floats2bfloat162_rn(acc[mt][nt][2], acc[mt][nt][3]);
            *reinterpret_cast<__nv_bfloat162*>(g_MAbf + (size_t)row * Dd + col) = lo;
            *reinterpret_cast<__nv_bfloat162*>(g_MAbf + (size_t)(row + 8) * Dd + col) = hi;
            float l0 = __bfloat162float(lo.x), l1 = __bfloat162float(lo.y);
            float h0 = __bfloat162float(hi.x), h1 = __bfloat162float(hi.y);
            s0 += l0 * l0 + l1 * l1;
            s1 += h0 * h0 + h1 * h1;
        }
        s0 += __shfl_xor_sync(0xFFFFFFFFu, s0, 1);
        s0 += __shfl_xor_sync(0xFFFFFFFFu, s0, 2);
        s1 += __shfl_xor_sync(0xFFFFFFFFu, s1, 1);
        s1 += __shfl_xor_sync(0xFFFFFFFFu, s1, 2);
        if ((lane & 3) == 0) {
            atomicAdd(&g_q[row], s0);
            atomicAdd(&g_q[row + 8], s1);
        }
    }
}

// ---------------------------------------------------------------------------
// 2) dot_mma (unchanged R16 winner): per-z direct stores, KS=4.
// ---------------------------------------------------------------------------
__global__ __launch_bounds__(128) void dot_mma() {
    __shared__ __align__(16) __nv_bfloat16 As[64][40];
    __shared__ __align__(16) __nv_bfloat16 Bs[64][40];
    int bm = blockIdx.x * 64;
    int bn = blockIdx.y * 64;
    int kb = blockIdx.z * KC;
    int tid = threadIdx.x;
    int lane = tid & 31, w = tid >> 5;
    int wm = (w & 1) * 32, wn = (w >> 1) * 32;

    int lr = tid >> 1;
    int lk = (tid & 1) * 16;
    const __nv_bfloat16* aptr = g_MAbf + (size_t)(Cc + bm + lr) * Dd + kb + lk;
    const __nv_bfloat16* bptr = g_MAbf + (size_t)(bn + lr) * Dd + kb + lk;

    float acc[2][4][4];
#pragma unroll
    for (int mt = 0; mt < 2; mt++)
#pragma unroll
        for (int nt = 0; nt < 4; nt++)
#pragma unroll
            for (int e = 0; e < 4; e++) acc[mt][nt][e] = 0.f;

    uint32_t aA[2], bA[2];
#pragma unroll
    for (int t2 = 0; t2 < 2; t2++) {
        aA[t2] = (uint32_t)__cvta_generic_to_shared(
            &As[wm + t2 * 16 + (lane & 15)][(lane >> 4) * 8]);
        bA[t2] = (uint32_t)__cvta_generic_to_shared(
            &Bs[wn + t2 * 16 + (lane & 15)][(lane >> 4) * 8]);
    }

    cudaGridDependencySynchronize();   // wait for gemm_ma_mma outputs

    uint4 pa0 = *reinterpret_cast<const uint4*>(aptr);
    uint4 pa1 = *reinterpret_cast<const uint4*>(aptr + 8);
    uint4 pb0 = *reinterpret_cast<const uint4*>(bptr);
    uint4 pb1 = *reinterpret_cast<const uint4*>(bptr + 8);

#pragma unroll 1
    for (int k0 = 0; k0 < KC; k0 += 32) {
        *reinterpret_cast<uint4*>(&As[lr][lk]) = pa0;
        *reinterpret_cast<uint4*>(&As[lr][lk + 8]) = pa1;
        *reinterpret_cast<uint4*>(&Bs[lr][lk]) = pb0;
        *reinterpret_cast<uint4*>(&Bs[lr][lk + 8]) = pb1;
        __syncthreads();
        if (k0 + 32 < KC) {
            pa0 = *reinterpret_cast<const uint4*>(aptr + k0 + 32);
            pa1 = *reinterpret_cast<const uint4*>(aptr + k0 + 40);
            pb0 = *reinterpret_cast<const uint4*>(bptr + k0 + 32);
            pb1 = *reinterpret_cast<const uint4*>(bptr + k0 + 40);
        }
#pragma unroll
        for (int ks = 0; ks < 2; ks++) {
            uint32_t off = (uint32_t)(ks * 32);
            uint32_t a0[4], a1[4], br0[4], br1[4];
            ldsm_x4(a0, aA[0] + off);
            ldsm_x4(a1, aA[1] + off);
            ldsm_x4(br0, bA[0] + off);
            ldsm_x4(br1, bA[1] + off);
#pragma unroll
            for (int mt = 0; mt < 2; mt++) {
                uint32_t* a = mt ? a1 : a0;
                mma_bf16(acc[mt][0], a, br0[0], br0[2]);
                mma_bf16(acc[mt][1], a, br0[1], br0[3]);
                mma_bf16(acc[mt][2], a, br1[0], br1[2]);
                mma_bf16(acc[mt][3], a, br1[1], br1[3]);
            }
        }
        __syncthreads();
    }

    int mrow = lane >> 2;
    int ncol = (lane & 3) * 2;
    float* outz = g_part + (size_t)blockIdx.z * Bb * Dd;
#pragma unroll
    for (int mt = 0; mt < 2; mt++)
#pragma unroll
        for (int nt = 0; nt < 4; nt++) {
            int row = bm + wm + mt * 16 + mrow;
            int col = bn + wn + nt * 8 + ncol;
            *reinterpret_cast<float2*>(outz + (size_t)row * Dd + col) =
                make_float2(acc[mt][nt][0], acc[mt][nt][1]);
            *reinterpret_cast<float2*>(outz + (size_t)(row + 8) * Dd + col) =
                make_float2(acc[mt][nt][2], acc[mt][nt][3]);
        }
}

// ---------------------------------------------------------------------------
// 3) Finalize (unchanged R16 winner): 4-slice sum, 2 c's per thread.
// ---------------------------------------------------------------------------
#define C2 (Cc / 2)   // 500
__global__ __launch_bounds__(128) void finalize(const float* __restrict__ lmbda,
                                                const float* __restrict__ scale,
                                                float* __restrict__ out) {
    int idx = blockIdx.x * 128 + threadIdx.x;
    int b = idx / C2;
    int c = (idx - b * C2) * 2;
    float lm = *lmbda;
    float sc = *scale;

    cudaGridDependencySynchronize();

    if (idx >= Bb * C2) return;

    float2 s = make_float2(0.f, 0.f);
#pragma unroll
    for (int z = 0; z < KS; z++) {
        float2 p = *reinterpret_cast<const float2*>(
            g_part + ((size_t)z * Bb + b) * Dd + c);
        s.x += p.x; s.y += p.y;
    }
    float2 qc = *reinterpret_cast<const float2*>(g_q + c);
    float2 bdc = *reinterpret_cast<const float2*>(g_bd + c);
    float qb = g_q[Cc + b];
    float bdb = g_bd[Cc + b];
    float2 o;
    {
        float quad = qb + qc.x - 2.f * s.x;
        float bd = bdb - bdc.x;
        o.x = -sc * (sqrtf(quad + 1e-6f) + lm * sqrtf(bd * bd + 1e-6f));
    }
    {
        float quad = qb + qc.y - 2.f * s.y;
        float bd = bdb - bdc.y;
        o.y = -sc * (sqrtf(quad + 1e-6f) + lm * sqrtf(bd * bd + 1e-6f));
    }
    *reinterpret_cast<float2*>(out + (size_t)b * Cc + c) = o;
}

// ---------------------------------------------------------------------------
extern "C" void kernel_launch(void* const* d_in, const int* in_sizes, int n_in,
                              void* d_out, int out_size) {
    const float *x = nullptr, *mu = nullptr, *beta = nullptr, *L = nullptr;
    const float *lmbda = nullptr, *scale = nullptr;
    for (int i = 0; i < n_in; i++) {
        const float* p = (const float*)d_in[i];
        switch (in_sizes[i]) {
            case Bb * Dd:  x = p; break;
            case Cc * Dd:  mu = p; break;
            case Dd:       beta = p; break;
            case Dd * Dd:  L = p; break;
            case 1:        if (!lmbda) lmbda = p; else scale = p; break;
            default: break;
        }
    }

    // Kernel 0: normal launch
    prep<<<MP + Dd, 256>>>(x, mu, beta, L);

    // Kernels 1-3: PDL (programmatic stream serialization)
    cudaLaunchAttribute attr[1];
    attr[0].id = cudaLaunchAttributeProgrammaticStreamSerialization;
    attr[0].val.programmaticStreamSerializationAllowed = 1;

    {
        cudaLaunchConfig_t cfg = {};
        cfg.gridDim = dim3(MP / 64, Dd / 64);
        cfg.blockDim = dim3(128);
        cfg.attrs = attr;
        cfg.numAttrs = 1;
        cudaLaunchKernelEx(&cfg, gemm_ma_mma);
    }
    {
        cudaLaunchConfig_t cfg = {};
        cfg.gridDim = dim3(Bb / 64, Dd / 64, KS);
        cfg.blockDim = dim3(128);
        cfg.attrs = attr;
        cfg.numAttrs = 1;
        cudaLaunchKernelEx(&cfg, dot_mma);
    }
    {
        cudaLaunchConfig_t cfg = {};
        cfg.gridDim = dim3((Bb * C2 + 127) / 128);
        cfg.blockDim = dim3(128);
        cfg.attrs = attr;
        cfg.numAttrs = 1;
        cudaLaunchKernelEx(&cfg, finalize, lmbda, scale, (float*)d_out);
    }
}